// round 15
// baseline (speedup 1.0000x reference)
#include <cuda_runtime.h>
#include <cuda_bf16.h>
#include <cstdint>

// ===========================================================================
// GRU cell via mma.sync (sm_103 non-'a' target: tcgen05 unavailable).
// 3-term bf16 split: C = Ah*Bh + Al*Bh + Ah*Bl  (~2^-17 effective precision).
// R15 = R14 (zero smem/barriers, fragment-direct A via LDG.128, B via LDG.64)
//       + A software-pipelined one half-step ahead: during half0's 18 mma we
//       load half1's fragments; during half1's mma we load next step's half0.
//       Every A load sits >=18 HMMA ahead of first use -> L1 latency hidden.
//   CTA tile M=64 x N=64, 256 threads = 8 warps (1m x 8n), warp m64 x n8.
//   2 CTAs/SM (register-bound), warps fully independent.
// ===========================================================================

#define NT_COUNT 8           // 512 / 64
#define MT_COUNT 256         // 16384 / 64

// packed A fragments: [mt 256][k16step 64][mtile 4][plane 2][lane 32][16B]
//   = 64 MB (+4KB pad so the pipelined "step 64" read is in-bounds).
//   Step s<32 from x, s>=32 from h.
__device__ __align__(128) unsigned char g_Afrag[256u * 64u * 4096u + 4096u];
// packed W: [nt 8][gate 3][chunk 32][plane 2][k16half 2][n 64][32B] = 6 MB
//   32B per (n, k16): pairs stored as (q, q+4) adjacent -> one LDG.64 = {b0,b1}
__device__ __align__(128) unsigned char g_Wpack[8u * 3u * 32u * 2u * 2u * 64u * 32u];

__device__ __forceinline__ void mma16(float c[4], const uint32_t a[4],
                                      uint32_t b0, uint32_t b1) {
    asm volatile(
        "mma.sync.aligned.m16n8k16.row.col.f32.bf16.bf16.f32 "
        "{%0,%1,%2,%3}, {%4,%5,%6,%7}, {%8,%9}, {%0,%1,%2,%3};\n"
        : "+f"(c[0]), "+f"(c[1]), "+f"(c[2]), "+f"(c[3])
        : "r"(a[0]), "r"(a[1]), "r"(a[2]), "r"(a[3]), "r"(b0), "r"(b1));
}

__device__ __forceinline__ uint32_t pack_hi(float a, float b, uint32_t& lo) {
    __nv_bfloat16 ha = __float2bfloat16(a);
    __nv_bfloat16 hb = __float2bfloat16(b);
    float ra = a - __bfloat162float(ha);
    float rb = b - __bfloat162float(hb);
    __nv_bfloat162 hw; hw.x = ha; hw.y = hb;
    __nv_bfloat162 lw = __floats2bfloat162_rn(ra, rb);
    lo = *reinterpret_cast<uint32_t*>(&lw);
    return *reinterpret_cast<uint32_t*>(&hw);
}

// ---------------------------------------------------------------------------
// Merged pack kernel (identical to R14).
// Blocks [0,2048): A fragments. Blocks [2048,2816): W part.
__global__ __launch_bounds__(256) void pack_all(
    const float* __restrict__ x, const float* __restrict__ hs,
    const float* __restrict__ Wir, const float* __restrict__ Whr,
    const float* __restrict__ Wiz, const float* __restrict__ Whz,
    const float* __restrict__ Win, const float* __restrict__ Whn) {
    __shared__ float stg[32][65];
    const int bx = blockIdx.x;
    if (bx < 2048) {
        const int mt = bx >> 3, sg = bx & 7;
        #pragma unroll
        for (int it = 0; it < 16; ++it) {
            int id = it * 256 + threadIdx.x;   // [0,4096)
            int j = id >> 9;                   // step within group
            int item = id & 511;
            int mtile = item >> 7;
            int lane_i = (item >> 2) & 31;
            int word = item & 3;
            int row = mtile * 16 + (lane_i >> 2) + (word & 1) * 8;
            int k = (lane_i & 3) * 2 + (word >> 1) * 8;
            int s = sg * 8 + j;
            const float* S = (s < 32) ? x : hs;
            int kglob = (s & 31) * 16 + k;
            float2 v = *reinterpret_cast<const float2*>(
                S + (size_t)(mt * 64 + row) * 512 + kglob);
            uint32_t lo, hi = pack_hi(v.x, v.y, lo);
            unsigned char* dst = g_Afrag + ((size_t)(mt * 64 + s)) * 4096
                               + (size_t)mtile * 1024 + (size_t)lane_i * 16
                               + (size_t)word * 4;
            *reinterpret_cast<uint32_t*>(dst)       = hi;   // plane 0 (hi)
            *reinterpret_cast<uint32_t*>(dst + 512) = lo;   // plane 1 (lo)
        }
    } else {
        const int w = bx - 2048;
        const int c = w & 31;
        const int ntg = w >> 5;                // 0..23 = nt*3 + g
        const int nt = ntg / 3, g = ntg % 3;
        const float* W = (c < 16)
            ? ((g == 0) ? Wir : (g == 1) ? Wiz : Win)
            : ((g == 0) ? Whr : (g == 1) ? Whz : Whn);
        const int k0 = (c & 15) * 32, n0 = nt * 64;
        #pragma unroll
        for (int it = 0; it < 8; ++it) {       // 2048 floats: 32k x 64n
            int id = it * 256 + threadIdx.x;
            int k = id >> 6, n = id & 63;
            stg[k][n] = W[(size_t)(k0 + k) * 512 + n0 + n];
        }
        __syncthreads();
        // write: [plane 2][h 2][n 64][32B]; pair p at byte (p&3)*8 + (p>>2)*4
        unsigned char* base = g_Wpack + (size_t)(ntg * 32 + c) * 8192;
        #pragma unroll
        for (int it = 0; it < 4; ++it) {       // 1024 pairs: 64n x 16kp
            int id = it * 256 + threadIdx.x;
            int n = id >> 4, kp = id & 15;
            int h = kp >> 3, pl = kp & 7;
            int off = h * 2048 + n * 32 + (pl & 3) * 8 + (pl >> 2) * 4;
            uint32_t lo, hi = pack_hi(stg[2 * kp][n], stg[2 * kp + 1][n], lo);
            *reinterpret_cast<uint32_t*>(base + off) = hi;
            *reinterpret_cast<uint32_t*>(base + 4096 + off) = lo;
        }
    }
}

// ---------------------------------------------------------------------------
// Load 6 B fragments (3 gates x hi/lo) for global k16-step g (clamped).
__device__ __forceinline__ void ldB(uint2 B[6], const unsigned char* bp, int g) {
    int c = g >> 1; if (c > 31) c = 31;
    const unsigned char* p = bp + (size_t)c * 8192 + (size_t)(g & 1) * 2048;
    B[0] = __ldg(reinterpret_cast<const uint2*>(p));
    B[1] = __ldg(reinterpret_cast<const uint2*>(p + 4096));
    B[2] = __ldg(reinterpret_cast<const uint2*>(p + 262144));
    B[3] = __ldg(reinterpret_cast<const uint2*>(p + 262144 + 4096));
    B[4] = __ldg(reinterpret_cast<const uint2*>(p + 524288));
    B[5] = __ldg(reinterpret_cast<const uint2*>(p + 524288 + 4096));
}

// A fragment set for one m32-half: hi/lo planes of two m16 tiles.
struct A16 { uint4 vh0, vl0, vh1, vl1; };

__device__ __forceinline__ void ldA(A16& A, const unsigned char* p) {
    A.vh0 = __ldg(reinterpret_cast<const uint4*>(p));
    A.vl0 = __ldg(reinterpret_cast<const uint4*>(p + 512));
    A.vh1 = __ldg(reinterpret_cast<const uint4*>(p + 1024));
    A.vl1 = __ldg(reinterpret_cast<const uint4*>(p + 1536));
}

// 18 mma for one m32-half (gate-interleaved, acc reuse distance 6).
__device__ __forceinline__ void mma_half(
    const A16& A, const uint2 B[6],
    float aR0[4], float aR1[4], float aZ0[4], float aZ1[4],
    float aN0[4], float aN1[4]) {
    const uint32_t* Ah0 = reinterpret_cast<const uint32_t*>(&A.vh0);
    const uint32_t* Al0 = reinterpret_cast<const uint32_t*>(&A.vl0);
    const uint32_t* Ah1 = reinterpret_cast<const uint32_t*>(&A.vh1);
    const uint32_t* Al1 = reinterpret_cast<const uint32_t*>(&A.vl1);
    // term 1: Ah x Bh
    mma16(aR0, Ah0, B[0].x, B[0].y);  mma16(aR1, Ah1, B[0].x, B[0].y);
    mma16(aZ0, Ah0, B[2].x, B[2].y);  mma16(aZ1, Ah1, B[2].x, B[2].y);
    mma16(aN0, Ah0, B[4].x, B[4].y);  mma16(aN1, Ah1, B[4].x, B[4].y);
    // term 2: Al x Bh
    mma16(aR0, Al0, B[0].x, B[0].y);  mma16(aR1, Al1, B[0].x, B[0].y);
    mma16(aZ0, Al0, B[2].x, B[2].y);  mma16(aZ1, Al1, B[2].x, B[2].y);
    mma16(aN0, Al0, B[4].x, B[4].y);  mma16(aN1, Al1, B[4].x, B[4].y);
    // term 3: Ah x Bl
    mma16(aR0, Ah0, B[1].x, B[1].y);  mma16(aR1, Ah1, B[1].x, B[1].y);
    mma16(aZ0, Ah0, B[3].x, B[3].y);  mma16(aZ1, Ah1, B[3].x, B[3].y);
    mma16(aN0, Ah0, B[5].x, B[5].y);  mma16(aN1, Ah1, B[5].x, B[5].y);
}

// One k16-step, A pipelined a half-step ahead:
//   ldB(next step); ldA(half1 of S); mma(half0, preloaded);
//   ldA(half0 of S+1); mma(half1).
#define STEPG(S, CUR, NXT, AN)                                            \
    do {                                                                  \
        ldB(NXT, bp, (S) + 1);                                            \
        ldA(Anx, ap + (size_t)(S) * 4096 + 2048);                         \
        mma_half(Acu, CUR, aR[0], aR[1], aZ[0], aZ[1], AN[0], AN[1]);     \
        ldA(Acu, ap + (size_t)((S) + 1) * 4096);                          \
        mma_half(Anx, CUR, aR[2], aR[3], aZ[2], aZ[3], AN[2], AN[3]);     \
    } while (0)

__global__ void __launch_bounds__(256, 2) gru_main(
    const float* __restrict__ hs,
    const float* __restrict__ br, const float* __restrict__ bz,
    const float* __restrict__ bn, float* __restrict__ out) {
    const int tid = threadIdx.x;
    const int wid = tid >> 5, lane = tid & 31;
    const int wn = wid * 8;               // 0..56
    const int nt = blockIdx.x;            // 0..7
    const int mt = blockIdx.y;            // 0..255

    const unsigned char* ap = g_Afrag + (size_t)mt * 64 * 4096
                            + (size_t)lane * 16;
    const unsigned char* bp = g_Wpack + (size_t)nt * 786432
        + (size_t)(wn + (lane >> 2)) * 32 + (size_t)(lane & 3) * 8;

    float aR[4][4] = {}, aZ[4][4] = {}, aNi[4][4] = {}, aNh[4][4] = {};
    uint2 B0[6], B1[6];
    A16 Acu, Anx;
    ldB(B0, bp, 0);
    ldA(Acu, ap);                         // step 0, half 0

    for (int s = 0; s < 32; s += 2) {     // x phase -> n_i
        STEPG(s,     B0, B1, aNi);
        STEPG(s + 1, B1, B0, aNi);
    }
    for (int s = 32; s < 64; s += 2) {    // h phase -> n_h
        STEPG(s,     B0, B1, aNh);
        STEPG(s + 1, B1, B0, aNh);
    }

    // ---- epilogue ----
    #pragma unroll
    for (int mtile = 0; mtile < 4; ++mtile)
    #pragma unroll
    for (int i = 0; i < 4; ++i) {
        int rr = mt * 64 + mtile * 16 + (lane >> 2) + ((i >> 1) << 3);
        int cc = nt * 64 + wn + 2 * (lane & 3) + (i & 1);
        float pr = aR[mtile][i] + __ldg(br + cc);
        float pz = aZ[mtile][i] + __ldg(bz + cc);
        float rg = 1.0f / (1.0f + __expf(-pr));
        float zg = 1.0f / (1.0f + __expf(-pz));
        float ng = tanhf(aNi[mtile][i] + rg * aNh[mtile][i] + __ldg(bn + cc));
        float hv = hs[(size_t)rr * 512 + cc];
        out[(size_t)rr * 512 + cc] = (1.0f - zg) * ng + zg * hv;
    }
}

// ---------------------------------------------------------------------------
extern "C" void kernel_launch(void* const* d_in, const int* in_sizes, int n_in,
                              void* d_out, int out_size) {
    (void)in_sizes; (void)n_in; (void)out_size;
    const float* x   = (const float*)d_in[0];
    const float* h   = (const float*)d_in[1];
    const float* Wir = (const float*)d_in[2];
    const float* Whr = (const float*)d_in[3];
    const float* br  = (const float*)d_in[4];
    const float* Wiz = (const float*)d_in[5];
    const float* Whz = (const float*)d_in[6];
    const float* bz  = (const float*)d_in[7];
    const float* Win = (const float*)d_in[8];
    const float* Whn = (const float*)d_in[9];
    const float* bn  = (const float*)d_in[10];

    pack_all<<<2816, 256>>>(x, h, Wir, Whr, Wiz, Whz, Win, Whn);
    gru_main<<<dim3(NT_COUNT, MT_COUNT), 256>>>(
        h, br, bz, bn, (float*)d_out);
}

// round 16
// speedup vs baseline: 1.2346x; 1.2346x over previous
#include <cuda_runtime.h>
#include <cuda_bf16.h>
#include <cstdint>

// ===========================================================================
// GRU cell via mma.sync (sm_103 non-'a' target: tcgen05 unavailable).
// 3-term bf16 split: C = Ah*Bh + Al*Bh + Ah*Bl  (~2^-17 effective precision).
// R16 = R14 (zero smem/barriers, fragment-direct A via LDG.128, B via LDG.64
//       double-buffered 1 step ahead) + prefetch.global.L1 of step s+2's A
//       and B lines (zero register cost) to hide L2 first-touch latency.
//   CTA tile M=64 x N=64, 256 threads = 8 warps (1m x 8n), warp m64 x n8.
//   2 CTAs/SM (register-bound), warps fully independent.
// ===========================================================================

#define NT_COUNT 8           // 512 / 64
#define MT_COUNT 256         // 16384 / 64

// packed A fragments: [mt 256][k16step 64][mtile 4][plane 2][lane 32][16B]
//   = 64 MB (+8KB pad so step s+2 prefetch needs no clamp).
//   Step s<32 from x, s>=32 from h.
__device__ __align__(128) unsigned char g_Afrag[256u * 64u * 4096u + 8192u];
// packed W: [nt 8][gate 3][chunk 32][plane 2][k16half 2][n 64][32B] = 6 MB
//   32B per (n, k16): pairs stored as (q, q+4) adjacent -> one LDG.64 = {b0,b1}
__device__ __align__(128) unsigned char g_Wpack[8u * 3u * 32u * 2u * 2u * 64u * 32u];

__device__ __forceinline__ void mma16(float c[4], const uint32_t a[4],
                                      uint32_t b0, uint32_t b1) {
    asm volatile(
        "mma.sync.aligned.m16n8k16.row.col.f32.bf16.bf16.f32 "
        "{%0,%1,%2,%3}, {%4,%5,%6,%7}, {%8,%9}, {%0,%1,%2,%3};\n"
        : "+f"(c[0]), "+f"(c[1]), "+f"(c[2]), "+f"(c[3])
        : "r"(a[0]), "r"(a[1]), "r"(a[2]), "r"(a[3]), "r"(b0), "r"(b1));
}

__device__ __forceinline__ void pf(const void* p) {
    asm volatile("prefetch.global.L1 [%0];" :: "l"(p));
}

__device__ __forceinline__ uint32_t pack_hi(float a, float b, uint32_t& lo) {
    __nv_bfloat16 ha = __float2bfloat16(a);
    __nv_bfloat16 hb = __float2bfloat16(b);
    float ra = a - __bfloat162float(ha);
    float rb = b - __bfloat162float(hb);
    __nv_bfloat162 hw; hw.x = ha; hw.y = hb;
    __nv_bfloat162 lw = __floats2bfloat162_rn(ra, rb);
    lo = *reinterpret_cast<uint32_t*>(&lw);
    return *reinterpret_cast<uint32_t*>(&hw);
}

// ---------------------------------------------------------------------------
// Merged pack kernel (identical to R14).
// Blocks [0,2048): A fragments. Blocks [2048,2816): W part.
__global__ __launch_bounds__(256) void pack_all(
    const float* __restrict__ x, const float* __restrict__ hs,
    const float* __restrict__ Wir, const float* __restrict__ Whr,
    const float* __restrict__ Wiz, const float* __restrict__ Whz,
    const float* __restrict__ Win, const float* __restrict__ Whn) {
    __shared__ float stg[32][65];
    const int bx = blockIdx.x;
    if (bx < 2048) {
        const int mt = bx >> 3, sg = bx & 7;
        #pragma unroll
        for (int it = 0; it < 16; ++it) {
            int id = it * 256 + threadIdx.x;   // [0,4096)
            int j = id >> 9;                   // step within group
            int item = id & 511;
            int mtile = item >> 7;
            int lane_i = (item >> 2) & 31;
            int word = item & 3;
            int row = mtile * 16 + (lane_i >> 2) + (word & 1) * 8;
            int k = (lane_i & 3) * 2 + (word >> 1) * 8;
            int s = sg * 8 + j;
            const float* S = (s < 32) ? x : hs;
            int kglob = (s & 31) * 16 + k;
            float2 v = *reinterpret_cast<const float2*>(
                S + (size_t)(mt * 64 + row) * 512 + kglob);
            uint32_t lo, hi = pack_hi(v.x, v.y, lo);
            unsigned char* dst = g_Afrag + ((size_t)(mt * 64 + s)) * 4096
                               + (size_t)mtile * 1024 + (size_t)lane_i * 16
                               + (size_t)word * 4;
            *reinterpret_cast<uint32_t*>(dst)       = hi;   // plane 0 (hi)
            *reinterpret_cast<uint32_t*>(dst + 512) = lo;   // plane 1 (lo)
        }
    } else {
        const int w = bx - 2048;
        const int c = w & 31;
        const int ntg = w >> 5;                // 0..23 = nt*3 + g
        const int nt = ntg / 3, g = ntg % 3;
        const float* W = (c < 16)
            ? ((g == 0) ? Wir : (g == 1) ? Wiz : Win)
            : ((g == 0) ? Whr : (g == 1) ? Whz : Whn);
        const int k0 = (c & 15) * 32, n0 = nt * 64;
        #pragma unroll
        for (int it = 0; it < 8; ++it) {       // 2048 floats: 32k x 64n
            int id = it * 256 + threadIdx.x;
            int k = id >> 6, n = id & 63;
            stg[k][n] = W[(size_t)(k0 + k) * 512 + n0 + n];
        }
        __syncthreads();
        // write: [plane 2][h 2][n 64][32B]; pair p at byte (p&3)*8 + (p>>2)*4
        unsigned char* base = g_Wpack + (size_t)(ntg * 32 + c) * 8192;
        #pragma unroll
        for (int it = 0; it < 4; ++it) {       // 1024 pairs: 64n x 16kp
            int id = it * 256 + threadIdx.x;
            int n = id >> 4, kp = id & 15;
            int h = kp >> 3, pl = kp & 7;
            int off = h * 2048 + n * 32 + (pl & 3) * 8 + (pl >> 2) * 4;
            uint32_t lo, hi = pack_hi(stg[2 * kp][n], stg[2 * kp + 1][n], lo);
            *reinterpret_cast<uint32_t*>(base + off) = hi;
            *reinterpret_cast<uint32_t*>(base + 4096 + off) = lo;
        }
    }
}

// ---------------------------------------------------------------------------
// Load 6 B fragments (3 gates x hi/lo) for global k16-step g (clamped).
__device__ __forceinline__ void ldB(uint2 B[6], const unsigned char* bp, int g) {
    int c = g >> 1; if (c > 31) c = 31;
    const unsigned char* p = bp + (size_t)c * 8192 + (size_t)(g & 1) * 2048;
    B[0] = __ldg(reinterpret_cast<const uint2*>(p));
    B[1] = __ldg(reinterpret_cast<const uint2*>(p + 4096));
    B[2] = __ldg(reinterpret_cast<const uint2*>(p + 262144));
    B[3] = __ldg(reinterpret_cast<const uint2*>(p + 262144 + 4096));
    B[4] = __ldg(reinterpret_cast<const uint2*>(p + 524288));
    B[5] = __ldg(reinterpret_cast<const uint2*>(p + 524288 + 4096));
}

// Prefetch B lines for global k16-step g into L1 (no registers written).
__device__ __forceinline__ void pfB(const unsigned char* bp, int g) {
    int c = g >> 1; if (c > 31) c = 31;
    const unsigned char* p = bp + (size_t)c * 8192 + (size_t)(g & 1) * 2048;
    pf(p);             pf(p + 4096);
    pf(p + 262144);    pf(p + 262144 + 4096);
    pf(p + 524288);    pf(p + 524288 + 4096);
}

// One m32-half: 4 LDG.128 (A frags direct from L1) + 18 mma
// (gate-interleaved, acc reuse distance 6). Layout per step-block:
//   [mtile 4][plane 2][512B]; half h uses mtiles 2h, 2h+1.
__device__ __forceinline__ void half_mma_g(
    const unsigned char* p, const uint2 B[6],
    float aR0[4], float aR1[4], float aZ0[4], float aZ1[4],
    float aN0[4], float aN1[4]) {
    uint4 vh0 = __ldg(reinterpret_cast<const uint4*>(p));
    uint4 vl0 = __ldg(reinterpret_cast<const uint4*>(p + 512));
    uint4 vh1 = __ldg(reinterpret_cast<const uint4*>(p + 1024));
    uint4 vl1 = __ldg(reinterpret_cast<const uint4*>(p + 1536));
    const uint32_t* Ah0 = reinterpret_cast<const uint32_t*>(&vh0);
    const uint32_t* Al0 = reinterpret_cast<const uint32_t*>(&vl0);
    const uint32_t* Ah1 = reinterpret_cast<const uint32_t*>(&vh1);
    const uint32_t* Al1 = reinterpret_cast<const uint32_t*>(&vl1);
    // term 1: Ah x Bh
    mma16(aR0, Ah0, B[0].x, B[0].y);  mma16(aR1, Ah1, B[0].x, B[0].y);
    mma16(aZ0, Ah0, B[2].x, B[2].y);  mma16(aZ1, Ah1, B[2].x, B[2].y);
    mma16(aN0, Ah0, B[4].x, B[4].y);  mma16(aN1, Ah1, B[4].x, B[4].y);
    // term 2: Al x Bh
    mma16(aR0, Al0, B[0].x, B[0].y);  mma16(aR1, Al1, B[0].x, B[0].y);
    mma16(aZ0, Al0, B[2].x, B[2].y);  mma16(aZ1, Al1, B[2].x, B[2].y);
    mma16(aN0, Al0, B[4].x, B[4].y);  mma16(aN1, Al1, B[4].x, B[4].y);
    // term 3: Ah x Bl
    mma16(aR0, Ah0, B[1].x, B[1].y);  mma16(aR1, Ah1, B[1].x, B[1].y);
    mma16(aZ0, Ah0, B[3].x, B[3].y);  mma16(aZ1, Ah1, B[3].x, B[3].y);
    mma16(aN0, Ah0, B[5].x, B[5].y);  mma16(aN1, Ah1, B[5].x, B[5].y);
}

#define STEPG(S, CUR, NXT, AN)                                            \
    do {                                                                  \
        ldB(NXT, bp, (S) + 1);                                            \
        pfB(bp, (S) + 2);                                                 \
        if (wid == 0) {                                                   \
            const unsigned char* qa = ap + (size_t)((S) + 2) * 4096;      \
            pf(qa);        pf(qa + 512);  pf(qa + 1024); pf(qa + 1536);   \
            pf(qa + 2048); pf(qa + 2560); pf(qa + 3072); pf(qa + 3584);   \
        }                                                                 \
        const unsigned char* sp = ap + (size_t)(S) * 4096;                \
        half_mma_g(sp,        CUR, aR[0], aR[1], aZ[0], aZ[1], AN[0], AN[1]); \
        half_mma_g(sp + 2048, CUR, aR[2], aR[3], aZ[2], aZ[3], AN[2], AN[3]); \
    } while (0)

__global__ void __launch_bounds__(256, 2) gru_main(
    const float* __restrict__ hs,
    const float* __restrict__ br, const float* __restrict__ bz,
    const float* __restrict__ bn, float* __restrict__ out) {
    const int tid = threadIdx.x;
    const int wid = tid >> 5, lane = tid & 31;
    const int wn = wid * 8;               // 0..56
    const int nt = blockIdx.x;            // 0..7
    const int mt = blockIdx.y;            // 0..255

    const unsigned char* ap = g_Afrag + (size_t)mt * 64 * 4096
                            + (size_t)lane * 16;
    const unsigned char* bp = g_Wpack + (size_t)nt * 786432
        + (size_t)(wn + (lane >> 2)) * 32 + (size_t)(lane & 3) * 8;

    float aR[4][4] = {}, aZ[4][4] = {}, aNi[4][4] = {}, aNh[4][4] = {};
    uint2 B0[6], B1[6];
    ldB(B0, bp, 0);

    for (int s = 0; s < 32; s += 2) {       // x phase -> n_i
        STEPG(s,     B0, B1, aNi);
        STEPG(s + 1, B1, B0, aNi);
    }
    for (int s = 32; s < 64; s += 2) {      // h phase -> n_h
        STEPG(s,     B0, B1, aNh);
        STEPG(s + 1, B1, B0, aNh);
    }

    // ---- epilogue ----
    #pragma unroll
    for (int mtile = 0; mtile < 4; ++mtile)
    #pragma unroll
    for (int i = 0; i < 4; ++i) {
        int rr = mt * 64 + mtile * 16 + (lane >> 2) + ((i >> 1) << 3);
        int cc = nt * 64 + wn + 2 * (lane & 3) + (i & 1);
        float pr = aR[mtile][i] + __ldg(br + cc);
        float pz = aZ[mtile][i] + __ldg(bz + cc);
        float rg = 1.0f / (1.0f + __expf(-pr));
        float zg = 1.0f / (1.0f + __expf(-pz));
        float ng = tanhf(aNi[mtile][i] + rg * aNh[mtile][i] + __ldg(bn + cc));
        float hv = hs[(size_t)rr * 512 + cc];
        out[(size_t)rr * 512 + cc] = (1.0f - zg) * ng + zg * hv;
    }
}

// ---------------------------------------------------------------------------
extern "C" void kernel_launch(void* const* d_in, const int* in_sizes, int n_in,
                              void* d_out, int out_size) {
    (void)in_sizes; (void)n_in; (void)out_size;
    const float* x   = (const float*)d_in[0];
    const float* h   = (const float*)d_in[1];
    const float* Wir = (const float*)d_in[2];
    const float* Whr = (const float*)d_in[3];
    const float* br  = (const float*)d_in[4];
    const float* Wiz = (const float*)d_in[5];
    const float* Whz = (const float*)d_in[6];
    const float* bz  = (const float*)d_in[7];
    const float* Win = (const float*)d_in[8];
    const float* Whn = (const float*)d_in[9];
    const float* bn  = (const float*)d_in[10];

    pack_all<<<2816, 256>>>(x, h, Wir, Whr, Wiz, Whz, Win, Whn);
    gru_main<<<dim3(NT_COUNT, MT_COUNT), 256>>>(
        h, br, bz, bn, (float*)d_out);
}

// round 17
// speedup vs baseline: 1.3748x; 1.1135x over previous
#include <cuda_runtime.h>
#include <cuda_bf16.h>
#include <cstdint>

// ===========================================================================
// GRU cell via mma.sync (sm_103 non-'a' target: tcgen05 unavailable).
// 3-term bf16 split: C = Ah*Bh + Al*Bh + Ah*Bl  (~2^-17 effective precision).
// R17 = R14 (zero smem/barriers, fragment-direct A via LDG.128) with the
// step restructured for load-latency distance at constant register cost:
//   - B-hi (terms 1-2) double-buffered one full step ahead (12 regs).
//   - B-lo (term 3 only) loaded just-in-time at step top (6 transient regs);
//     first use is >=20 issue slots downstream -> L2 latency covered.
//   - BOTH m32-halves' A fragments front-loaded at step top (32 transient
//     regs); A1 sits 18 mma ahead of use, A0's stall consolidates.
//   Peak live regs ~120 < 128 -> no spill (the R6/R15 failure mode).
//   CTA tile M=64 x N=64, 256 threads = 8 warps (1m x 8n), warp m64 x n8.
//   2 CTAs/SM, warps fully independent.
// ===========================================================================

#define NT_COUNT 8           // 512 / 64
#define MT_COUNT 256         // 16384 / 64

// packed A fragments: [mt 256][k16step 64][mtile 4][plane 2][lane 32][16B]
//   = 64 MB (+4KB pad).  Step s<32 from x, s>=32 from h.
__device__ __align__(128) unsigned char g_Afrag[256u * 64u * 4096u + 4096u];
// packed W: [nt 8][gate 3][chunk 32][plane 2][k16half 2][n 64][32B] = 6 MB
//   32B per (n, k16): pairs stored as (q, q+4) adjacent -> one LDG.64 = {b0,b1}
__device__ __align__(128) unsigned char g_Wpack[8u * 3u * 32u * 2u * 2u * 64u * 32u];

__device__ __forceinline__ void mma16(float c[4], const uint32_t a[4],
                                      uint32_t b0, uint32_t b1) {
    asm volatile(
        "mma.sync.aligned.m16n8k16.row.col.f32.bf16.bf16.f32 "
        "{%0,%1,%2,%3}, {%4,%5,%6,%7}, {%8,%9}, {%0,%1,%2,%3};\n"
        : "+f"(c[0]), "+f"(c[1]), "+f"(c[2]), "+f"(c[3])
        : "r"(a[0]), "r"(a[1]), "r"(a[2]), "r"(a[3]), "r"(b0), "r"(b1));
}

__device__ __forceinline__ uint32_t pack_hi(float a, float b, uint32_t& lo) {
    __nv_bfloat16 ha = __float2bfloat16(a);
    __nv_bfloat16 hb = __float2bfloat16(b);
    float ra = a - __bfloat162float(ha);
    float rb = b - __bfloat162float(hb);
    __nv_bfloat162 hw; hw.x = ha; hw.y = hb;
    __nv_bfloat162 lw = __floats2bfloat162_rn(ra, rb);
    lo = *reinterpret_cast<uint32_t*>(&lw);
    return *reinterpret_cast<uint32_t*>(&hw);
}

// ---------------------------------------------------------------------------
// Merged pack kernel (identical to R14).
// Blocks [0,2048): A fragments. Blocks [2048,2816): W part.
__global__ __launch_bounds__(256) void pack_all(
    const float* __restrict__ x, const float* __restrict__ hs,
    const float* __restrict__ Wir, const float* __restrict__ Whr,
    const float* __restrict__ Wiz, const float* __restrict__ Whz,
    const float* __restrict__ Win, const float* __restrict__ Whn) {
    __shared__ float stg[32][65];
    const int bx = blockIdx.x;
    if (bx < 2048) {
        const int mt = bx >> 3, sg = bx & 7;
        #pragma unroll
        for (int it = 0; it < 16; ++it) {
            int id = it * 256 + threadIdx.x;   // [0,4096)
            int j = id >> 9;                   // step within group
            int item = id & 511;
            int mtile = item >> 7;
            int lane_i = (item >> 2) & 31;
            int word = item & 3;
            int row = mtile * 16 + (lane_i >> 2) + (word & 1) * 8;
            int k = (lane_i & 3) * 2 + (word >> 1) * 8;
            int s = sg * 8 + j;
            const float* S = (s < 32) ? x : hs;
            int kglob = (s & 31) * 16 + k;
            float2 v = *reinterpret_cast<const float2*>(
                S + (size_t)(mt * 64 + row) * 512 + kglob);
            uint32_t lo, hi = pack_hi(v.x, v.y, lo);
            unsigned char* dst = g_Afrag + ((size_t)(mt * 64 + s)) * 4096
                               + (size_t)mtile * 1024 + (size_t)lane_i * 16
                               + (size_t)word * 4;
            *reinterpret_cast<uint32_t*>(dst)       = hi;   // plane 0 (hi)
            *reinterpret_cast<uint32_t*>(dst + 512) = lo;   // plane 1 (lo)
        }
    } else {
        const int w = bx - 2048;
        const int c = w & 31;
        const int ntg = w >> 5;                // 0..23 = nt*3 + g
        const int nt = ntg / 3, g = ntg % 3;
        const float* W = (c < 16)
            ? ((g == 0) ? Wir : (g == 1) ? Wiz : Win)
            : ((g == 0) ? Whr : (g == 1) ? Whz : Whn);
        const int k0 = (c & 15) * 32, n0 = nt * 64;
        #pragma unroll
        for (int it = 0; it < 8; ++it) {       // 2048 floats: 32k x 64n
            int id = it * 256 + threadIdx.x;
            int k = id >> 6, n = id & 63;
            stg[k][n] = W[(size_t)(k0 + k) * 512 + n0 + n];
        }
        __syncthreads();
        // write: [plane 2][h 2][n 64][32B]; pair p at byte (p&3)*8 + (p>>2)*4
        unsigned char* base = g_Wpack + (size_t)(ntg * 32 + c) * 8192;
        #pragma unroll
        for (int it = 0; it < 4; ++it) {       // 1024 pairs: 64n x 16kp
            int id = it * 256 + threadIdx.x;
            int n = id >> 4, kp = id & 15;
            int h = kp >> 3, pl = kp & 7;
            int off = h * 2048 + n * 32 + (pl & 3) * 8 + (pl >> 2) * 4;
            uint32_t lo, hi = pack_hi(stg[2 * kp][n], stg[2 * kp + 1][n], lo);
            *reinterpret_cast<uint32_t*>(base + off) = hi;
            *reinterpret_cast<uint32_t*>(base + 4096 + off) = lo;
        }
    }
}

// ---------------------------------------------------------------------------
// B-hi fragments (3 gates) for global k16-step g (clamped).
__device__ __forceinline__ void ldB3hi(uint2 B[3], const unsigned char* bp, int g) {
    int c = g >> 1; if (c > 31) c = 31;
    const unsigned char* p = bp + (size_t)c * 8192 + (size_t)(g & 1) * 2048;
    B[0] = __ldg(reinterpret_cast<const uint2*>(p));
    B[1] = __ldg(reinterpret_cast<const uint2*>(p + 262144));
    B[2] = __ldg(reinterpret_cast<const uint2*>(p + 524288));
}
// B-lo fragments (3 gates) for global k16-step g.
__device__ __forceinline__ void ldB3lo(uint2 B[3], const unsigned char* bp, int g) {
    const unsigned char* p = bp + (size_t)(g >> 1) * 8192
                           + (size_t)(g & 1) * 2048 + 4096;
    B[0] = __ldg(reinterpret_cast<const uint2*>(p));
    B[1] = __ldg(reinterpret_cast<const uint2*>(p + 262144));
    B[2] = __ldg(reinterpret_cast<const uint2*>(p + 524288));
}

// A fragment set for one m32-half: hi/lo planes of two m16 tiles.
struct A16 { uint4 vh0, vl0, vh1, vl1; };

__device__ __forceinline__ void ldA(A16& A, const unsigned char* p) {
    A.vh0 = __ldg(reinterpret_cast<const uint4*>(p));
    A.vl0 = __ldg(reinterpret_cast<const uint4*>(p + 512));
    A.vh1 = __ldg(reinterpret_cast<const uint4*>(p + 1024));
    A.vl1 = __ldg(reinterpret_cast<const uint4*>(p + 1536));
}

// 18 mma for one m32-half (gate-interleaved, acc reuse distance 6).
// Same per-accumulator term order as R14 -> bit-identical results.
__device__ __forceinline__ void mma_half(
    const A16& A, const uint2 Bh[3], const uint2 Bl[3],
    float aR0[4], float aR1[4], float aZ0[4], float aZ1[4],
    float aN0[4], float aN1[4]) {
    const uint32_t* Ah0 = reinterpret_cast<const uint32_t*>(&A.vh0);
    const uint32_t* Al0 = reinterpret_cast<const uint32_t*>(&A.vl0);
    const uint32_t* Ah1 = reinterpret_cast<const uint32_t*>(&A.vh1);
    const uint32_t* Al1 = reinterpret_cast<const uint32_t*>(&A.vl1);
    // term 1: Ah x Bh
    mma16(aR0, Ah0, Bh[0].x, Bh[0].y);  mma16(aR1, Ah1, Bh[0].x, Bh[0].y);
    mma16(aZ0, Ah0, Bh[1].x, Bh[1].y);  mma16(aZ1, Ah1, Bh[1].x, Bh[1].y);
    mma16(aN0, Ah0, Bh[2].x, Bh[2].y);  mma16(aN1, Ah1, Bh[2].x, Bh[2].y);
    // term 2: Al x Bh
    mma16(aR0, Al0, Bh[0].x, Bh[0].y);  mma16(aR1, Al1, Bh[0].x, Bh[0].y);
    mma16(aZ0, Al0, Bh[1].x, Bh[1].y);  mma16(aZ1, Al1, Bh[1].x, Bh[1].y);
    mma16(aN0, Al0, Bh[2].x, Bh[2].y);  mma16(aN1, Al1, Bh[2].x, Bh[2].y);
    // term 3: Ah x Bl
    mma16(aR0, Ah0, Bl[0].x, Bl[0].y);  mma16(aR1, Ah1, Bl[0].x, Bl[0].y);
    mma16(aZ0, Ah0, Bl[1].x, Bl[1].y);  mma16(aZ1, Ah1, Bl[1].x, Bl[1].y);
    mma16(aN0, Ah0, Bl[2].x, Bl[2].y);  mma16(aN1, Ah1, Bl[2].x, Bl[2].y);
}

// One k16-step:
//   ldB3hi(s+1) -> next-step hi prefetch (full-step distance)
//   ldB3lo(s)   -> this step's lo, first used in term 3 (>=20 slots away)
//   ldA(A0), ldA(A1) -> both halves front-loaded; A1 sits 18 mma ahead
//   mma half0, mma half1
#define STEPG(S, CUR, NXT, AN)                                            \
    do {                                                                  \
        ldB3hi(NXT, bp, (S) + 1);                                         \
        uint2 BL[3];                                                      \
        ldB3lo(BL, bp, (S));                                              \
        const unsigned char* sp = ap + (size_t)(S) * 4096;                \
        A16 A0, A1;                                                       \
        ldA(A0, sp);                                                      \
        ldA(A1, sp + 2048);                                               \
        mma_half(A0, CUR, BL, aR[0], aR[1], aZ[0], aZ[1], AN[0], AN[1]);  \
        mma_half(A1, CUR, BL, aR[2], aR[3], aZ[2], aZ[3], AN[2], AN[3]);  \
    } while (0)

__global__ void __launch_bounds__(256, 2) gru_main(
    const float* __restrict__ hs,
    const float* __restrict__ br, const float* __restrict__ bz,
    const float* __restrict__ bn, float* __restrict__ out) {
    const int tid = threadIdx.x;
    const int wid = tid >> 5, lane = tid & 31;
    const int wn = wid * 8;               // 0..56
    const int nt = blockIdx.x;            // 0..7
    const int mt = blockIdx.y;            // 0..255

    const unsigned char* ap = g_Afrag + (size_t)mt * 64 * 4096
                            + (size_t)lane * 16;
    const unsigned char* bp = g_Wpack + (size_t)nt * 786432
        + (size_t)(wn + (lane >> 2)) * 32 + (size_t)(lane & 3) * 8;

    float aR[4][4] = {}, aZ[4][4] = {}, aNi[4][4] = {}, aNh[4][4] = {};
    uint2 Bh0[3], Bh1[3];
    ldB3hi(Bh0, bp, 0);

    for (int s = 0; s < 32; s += 2) {       // x phase -> n_i
        STEPG(s,     Bh0, Bh1, aNi);
        STEPG(s + 1, Bh1, Bh0, aNi);
    }
    for (int s = 32; s < 64; s += 2) {      // h phase -> n_h
        STEPG(s,     Bh0, Bh1, aNh);
        STEPG(s + 1, Bh1, Bh0, aNh);
    }

    // ---- epilogue ----
    #pragma unroll
    for (int mtile = 0; mtile < 4; ++mtile)
    #pragma unroll
    for (int i = 0; i < 4; ++i) {
        int rr = mt * 64 + mtile * 16 + (lane >> 2) + ((i >> 1) << 3);
        int cc = nt * 64 + wn + 2 * (lane & 3) + (i & 1);
        float pr = aR[mtile][i] + __ldg(br + cc);
        float pz = aZ[mtile][i] + __ldg(bz + cc);
        float rg = 1.0f / (1.0f + __expf(-pr));
        float zg = 1.0f / (1.0f + __expf(-pz));
        float ng = tanhf(aNi[mtile][i] + rg * aNh[mtile][i] + __ldg(bn + cc));
        float hv = hs[(size_t)rr * 512 + cc];
        out[(size_t)rr * 512 + cc] = (1.0f - zg) * ng + zg * hv;
    }
}

// ---------------------------------------------------------------------------
extern "C" void kernel_launch(void* const* d_in, const int* in_sizes, int n_in,
                              void* d_out, int out_size) {
    (void)in_sizes; (void)n_in; (void)out_size;
    const float* x   = (const float*)d_in[0];
    const float* h   = (const float*)d_in[1];
    const float* Wir = (const float*)d_in[2];
    const float* Whr = (const float*)d_in[3];
    const float* br  = (const float*)d_in[4];
    const float* Wiz = (const float*)d_in[5];
    const float* Whz = (const float*)d_in[6];
    const float* bz  = (const float*)d_in[7];
    const float* Win = (const float*)d_in[8];
    const float* Whn = (const float*)d_in[9];
    const float* bn  = (const float*)d_in[10];

    pack_all<<<2816, 256>>>(x, h, Wir, Whr, Wiz, Whz, Win, Whn);
    gru_main<<<dim3(NT_COUNT, MT_COUNT), 256>>>(
        h, br, bz, bn, (float*)d_out);
}